// round 12
// baseline (speedup 1.0000x reference)
#include <cuda_runtime.h>
#include <cuda_fp16.h>
#include <math.h>

#define NNODES 50000
#define NEDGES 800000
#define FEAT   120

// Scratch (static __device__ arrays — allocation-free per harness rules)
__device__ __half2 g_qWh[(size_t)NNODES * FEAT * 2]; // [n][f][4 heads as 2x half2], 48 MB
__device__ __half  g_kh [(size_t)NNODES * FEAT];     // 12 MB
__device__ float   g_v  [(size_t)NNODES * FEAT];     // 24 MB
__device__ float   g_z  [NNODES];

__device__ __forceinline__ void store_qw(int n, int f, float4 a, float c) {
    __half2 h01 = __floats2half2_rn(a.x * c, a.y * c);
    __half2 h23 = __floats2half2_rn(a.z * c, a.w * c);
    uint2 u;
    u.x = *reinterpret_cast<unsigned*>(&h01);
    u.y = *reinterpret_cast<unsigned*>(&h23);
    reinterpret_cast<uint2*>(g_qWh)[(size_t)n * FEAT + f] = u;
}

// Wd contraction for a node pair; q values read from 4-paired smem layout at
// component offset `off` (0 -> nodes {0,1}, 2 -> nodes {2,3}).
__device__ __forceinline__ void wd_pair(
    const float* __restrict__ qs, int na, int nb, int off, int lane,
    const float4* __restrict__ D0, const float4* __restrict__ D1,
    const float4* __restrict__ D2)
{
    const float c0 = 0.02176061898f;     // 1/sqrt(2112)
    const float c1 = c0 * 0.5773502692f; // c0/sqrt(3)
    const float c2 = c0 * 0.4472135955f; // c0/sqrt(5)

    // l=0: j = lane
    {
        float4 A0 = make_float4(0.f,0.f,0.f,0.f);
        float4 A1 = make_float4(0.f,0.f,0.f,0.f);
        #pragma unroll
        for (int i = 0; i < 32; ++i) {
            float4 w = __ldg(&D0[i * 32 + lane]);
            float2 qv = *reinterpret_cast<const float2*>(&qs[4 * i + off]);
            A0.x += qv.x*w.x; A0.y += qv.x*w.y; A0.z += qv.x*w.z; A0.w += qv.x*w.w;
            A1.x += qv.y*w.x; A1.y += qv.y*w.y; A1.z += qv.y*w.z; A1.w += qv.y*w.w;
        }
        store_qw(na, lane, A0, c0);
        store_qw(nb, lane, A1, c0);
    }
    // l=1: lanes 0..15, j = lane
    if (lane < 16) {
        float4 B0[3], B1[3];
        #pragma unroll
        for (int m = 0; m < 3; ++m) {
            B0[m] = make_float4(0.f,0.f,0.f,0.f);
            B1[m] = make_float4(0.f,0.f,0.f,0.f);
        }
        #pragma unroll
        for (int i = 0; i < 16; ++i) {
            float4 w = __ldg(&D1[i * 16 + lane]);
            #pragma unroll
            for (int m = 0; m < 3; ++m) {
                float2 qv = *reinterpret_cast<const float2*>(&qs[4 * (32 + i*3 + m) + off]);
                B0[m].x += qv.x*w.x; B0[m].y += qv.x*w.y; B0[m].z += qv.x*w.z; B0[m].w += qv.x*w.w;
                B1[m].x += qv.y*w.x; B1[m].y += qv.y*w.y; B1[m].z += qv.y*w.z; B1[m].w += qv.y*w.w;
            }
        }
        #pragma unroll
        for (int m = 0; m < 3; ++m) {
            int f = 32 + lane*3 + m;
            store_qw(na, f, B0[m], c1);
            store_qw(nb, f, B1[m], c1);
        }
    }
    // l=2: lanes 16..23, j = lane-16
    else if (lane < 24) {
        const int j = lane - 16;
        float4 C0[5], C1[5];
        #pragma unroll
        for (int m = 0; m < 5; ++m) {
            C0[m] = make_float4(0.f,0.f,0.f,0.f);
            C1[m] = make_float4(0.f,0.f,0.f,0.f);
        }
        #pragma unroll
        for (int i = 0; i < 8; ++i) {
            float4 w = __ldg(&D2[i * 8 + j]);
            #pragma unroll
            for (int m = 0; m < 5; ++m) {
                float2 qv = *reinterpret_cast<const float2*>(&qs[4 * (80 + i*5 + m) + off]);
                C0[m].x += qv.x*w.x; C0[m].y += qv.x*w.y; C0[m].z += qv.x*w.z; C0[m].w += qv.x*w.w;
                C1[m].x += qv.y*w.x; C1[m].y += qv.y*w.y; C1[m].z += qv.y*w.z; C1[m].w += qv.y*w.w;
            }
        }
        #pragma unroll
        for (int m = 0; m < 5; ++m) {
            int f = 80 + j*5 + m;
            store_qw(na, f, C0[m], c2);
            store_qw(nb, f, C1[m], c2);
        }
    }
}

// ---------------------------------------------------------------------------
// Node kernel: FOUR nodes per warp, 10 warps (40 nodes) per block.
// 50000 = 40 * 1250 exactly -> no bounds checks.
// Node-quad smem layout [f][4]: one LDS.128 broadcast serves all 4 nodes;
// each weight load feeds 4 independent FMA chains.
// ---------------------------------------------------------------------------
__global__ __launch_bounds__(320) void node_kernel(
    const float* __restrict__ x,
    const float* __restrict__ Wq0, const float* __restrict__ Wq1, const float* __restrict__ Wq2,
    const float* __restrict__ Wk0, const float* __restrict__ Wk1, const float* __restrict__ Wk2,
    const float* __restrict__ Wv0, const float* __restrict__ Wv1, const float* __restrict__ Wv2,
    const float* __restrict__ Wd0, const float* __restrict__ Wd1, const float* __restrict__ Wd2,
    float* __restrict__ out)
{
    __shared__ __align__(16) float sX[10][FEAT * 4];   // [warp][f*4 + node]
    __shared__ __align__(16) float sQ[10][FEAT * 4];

    const int warp = threadIdx.x >> 5;
    const int lane = threadIdx.x & 31;
    const int n0 = blockIdx.x * 40 + warp * 4;

    float* xs = sX[warp];
    float* qs = sQ[warp];
    const float4* xs4 = reinterpret_cast<const float4*>(xs);

    for (int f = lane; f < FEAT; f += 32) {
        float4 xv;
        xv.x = x[(size_t)(n0+0) * FEAT + f];
        xv.y = x[(size_t)(n0+1) * FEAT + f];
        xv.z = x[(size_t)(n0+2) * FEAT + f];
        xv.w = x[(size_t)(n0+3) * FEAT + f];
        *reinterpret_cast<float4*>(&xs[4 * f]) = xv;
        out[(size_t)(n0+0) * FEAT + f] = 0.0f;   // out accumulates edge sums
        out[(size_t)(n0+1) * FEAT + f] = 0.0f;
        out[(size_t)(n0+2) * FEAT + f] = 0.0f;
        out[(size_t)(n0+3) * FEAT + f] = 0.0f;
    }
    if (lane < 4) g_z[n0 + lane] = 0.0f;
    __syncwarp();

    const float inv_s32 = 0.1767766953f;   // 1/sqrt(32)
    const float inv_s16 = 0.25f;
    const float inv_s8  = 0.3535533906f;   // 1/sqrt(8)

    #pragma unroll 1
    for (int pass = 0; pass < 3; ++pass) {
        const float* W0 = (pass == 0) ? Wq0 : ((pass == 1) ? Wk0 : Wv0);
        const float* W1 = (pass == 0) ? Wq1 : ((pass == 1) ? Wk1 : Wv1);
        const float* W2 = (pass == 0) ? Wq2 : ((pass == 1) ? Wk2 : Wv2);

        // l=0: output j = lane
        {
            float a0 = 0.f, a1 = 0.f, a2 = 0.f, a3 = 0.f;
            #pragma unroll
            for (int i = 0; i < 32; ++i) {
                float4 xv = xs4[i];
                float w = __ldg(&W0[i * 32 + lane]);
                a0 += xv.x * w; a1 += xv.y * w; a2 += xv.z * w; a3 += xv.w * w;
            }
            a0 *= inv_s32; a1 *= inv_s32; a2 *= inv_s32; a3 *= inv_s32;
            float nn0 = sqrtf(a0*a0 + 1e-10f), nn1 = sqrtf(a1*a1 + 1e-10f);
            float nn2 = sqrtf(a2*a2 + 1e-10f), nn3 = sqrtf(a3*a3 + 1e-10f);
            float y0 = (1.0f / (1.0f + __expf(-nn0))) / nn0 * a0;
            float y1 = (1.0f / (1.0f + __expf(-nn1))) / nn1 * a1;
            float y2 = (1.0f / (1.0f + __expf(-nn2))) / nn2 * a2;
            float y3 = (1.0f / (1.0f + __expf(-nn3))) / nn3 * a3;
            if (pass == 0) {
                *reinterpret_cast<float4*>(&qs[4 * lane]) = make_float4(y0, y1, y2, y3);
            } else if (pass == 1) {
                g_kh[(size_t)(n0+0) * FEAT + lane] = __float2half_rn(y0);
                g_kh[(size_t)(n0+1) * FEAT + lane] = __float2half_rn(y1);
                g_kh[(size_t)(n0+2) * FEAT + lane] = __float2half_rn(y2);
                g_kh[(size_t)(n0+3) * FEAT + lane] = __float2half_rn(y3);
            } else {
                g_v[(size_t)(n0+0) * FEAT + lane] = y0;
                g_v[(size_t)(n0+1) * FEAT + lane] = y1;
                g_v[(size_t)(n0+2) * FEAT + lane] = y2;
                g_v[(size_t)(n0+3) * FEAT + lane] = y3;
            }
        }
        // l=1: lanes 0..15, output j = lane
        if (lane < 16) {
            float r0[3], r1[3], r2[3], r3[3];
            #pragma unroll
            for (int m = 0; m < 3; ++m) { r0[m]=0.f; r1[m]=0.f; r2[m]=0.f; r3[m]=0.f; }
            #pragma unroll
            for (int i = 0; i < 16; ++i) {
                float w = __ldg(&W1[i * 16 + lane]);
                #pragma unroll
                for (int m = 0; m < 3; ++m) {
                    float4 xv = xs4[32 + i*3 + m];
                    r0[m] += xv.x * w; r1[m] += xv.y * w;
                    r2[m] += xv.z * w; r3[m] += xv.w * w;
                }
            }
            float ss0=0.f, ss1=0.f, ss2=0.f, ss3=0.f;
            #pragma unroll
            for (int m = 0; m < 3; ++m) {
                r0[m]*=inv_s16; r1[m]*=inv_s16; r2[m]*=inv_s16; r3[m]*=inv_s16;
                ss0+=r0[m]*r0[m]; ss1+=r1[m]*r1[m]; ss2+=r2[m]*r2[m]; ss3+=r3[m]*r3[m];
            }
            float nn0=sqrtf(ss0+1e-10f), nn1=sqrtf(ss1+1e-10f);
            float nn2=sqrtf(ss2+1e-10f), nn3=sqrtf(ss3+1e-10f);
            float sc0=(1.0f/(1.0f+__expf(-nn0)))/nn0;
            float sc1=(1.0f/(1.0f+__expf(-nn1)))/nn1;
            float sc2=(1.0f/(1.0f+__expf(-nn2)))/nn2;
            float sc3=(1.0f/(1.0f+__expf(-nn3)))/nn3;
            #pragma unroll
            for (int m = 0; m < 3; ++m) {
                int f = 32 + lane*3 + m;
                float y0=sc0*r0[m], y1=sc1*r1[m], y2=sc2*r2[m], y3=sc3*r3[m];
                if (pass == 0) {
                    *reinterpret_cast<float4*>(&qs[4 * f]) = make_float4(y0, y1, y2, y3);
                } else if (pass == 1) {
                    g_kh[(size_t)(n0+0) * FEAT + f] = __float2half_rn(y0);
                    g_kh[(size_t)(n0+1) * FEAT + f] = __float2half_rn(y1);
                    g_kh[(size_t)(n0+2) * FEAT + f] = __float2half_rn(y2);
                    g_kh[(size_t)(n0+3) * FEAT + f] = __float2half_rn(y3);
                } else {
                    g_v[(size_t)(n0+0) * FEAT + f] = y0;
                    g_v[(size_t)(n0+1) * FEAT + f] = y1;
                    g_v[(size_t)(n0+2) * FEAT + f] = y2;
                    g_v[(size_t)(n0+3) * FEAT + f] = y3;
                }
            }
        }
        // l=2: lanes 16..23, output j = lane-16
        else if (lane < 24) {
            const int j = lane - 16;
            float r0[5], r1[5], r2[5], r3[5];
            #pragma unroll
            for (int m = 0; m < 5; ++m) { r0[m]=0.f; r1[m]=0.f; r2[m]=0.f; r3[m]=0.f; }
            #pragma unroll
            for (int i = 0; i < 8; ++i) {
                float w = __ldg(&W2[i * 8 + j]);
                #pragma unroll
                for (int m = 0; m < 5; ++m) {
                    float4 xv = xs4[80 + i*5 + m];
                    r0[m] += xv.x * w; r1[m] += xv.y * w;
                    r2[m] += xv.z * w; r3[m] += xv.w * w;
                }
            }
            float ss0=0.f, ss1=0.f, ss2=0.f, ss3=0.f;
            #pragma unroll
            for (int m = 0; m < 5; ++m) {
                r0[m]*=inv_s8; r1[m]*=inv_s8; r2[m]*=inv_s8; r3[m]*=inv_s8;
                ss0+=r0[m]*r0[m]; ss1+=r1[m]*r1[m]; ss2+=r2[m]*r2[m]; ss3+=r3[m]*r3[m];
            }
            float nn0=sqrtf(ss0+1e-10f), nn1=sqrtf(ss1+1e-10f);
            float nn2=sqrtf(ss2+1e-10f), nn3=sqrtf(ss3+1e-10f);
            float sc0=(1.0f/(1.0f+__expf(-nn0)))/nn0;
            float sc1=(1.0f/(1.0f+__expf(-nn1)))/nn1;
            float sc2=(1.0f/(1.0f+__expf(-nn2)))/nn2;
            float sc3=(1.0f/(1.0f+__expf(-nn3)))/nn3;
            #pragma unroll
            for (int m = 0; m < 5; ++m) {
                int f = 80 + j*5 + m;
                float y0=sc0*r0[m], y1=sc1*r1[m], y2=sc2*r2[m], y3=sc3*r3[m];
                if (pass == 0) {
                    *reinterpret_cast<float4*>(&qs[4 * f]) = make_float4(y0, y1, y2, y3);
                } else if (pass == 1) {
                    g_kh[(size_t)(n0+0) * FEAT + f] = __float2half_rn(y0);
                    g_kh[(size_t)(n0+1) * FEAT + f] = __float2half_rn(y1);
                    g_kh[(size_t)(n0+2) * FEAT + f] = __float2half_rn(y2);
                    g_kh[(size_t)(n0+3) * FEAT + f] = __float2half_rn(y3);
                } else {
                    g_v[(size_t)(n0+0) * FEAT + f] = y0;
                    g_v[(size_t)(n0+1) * FEAT + f] = y1;
                    g_v[(size_t)(n0+2) * FEAT + f] = y2;
                    g_v[(size_t)(n0+3) * FEAT + f] = y3;
                }
            }
        }
        __syncwarp();
    }

    // ---- Wd contraction: two pair-passes over the node quad ----
    const float4* D0 = reinterpret_cast<const float4*>(Wd0);
    const float4* D1 = reinterpret_cast<const float4*>(Wd1);
    const float4* D2 = reinterpret_cast<const float4*>(Wd2);
    wd_pair(qs, n0 + 0, n0 + 1, 0, lane, D0, D1, D2);
    wd_pair(qs, n0 + 2, n0 + 3, 2, lane, D0, D1, D2);
}

// ---------------------------------------------------------------------------
// Fused edge kernel (R4 verbatim): one warp per edge.
// ev = mean_h exp(qW[dst]·k[src]); z[dst] += ev; out[dst] += sqrt(ev)*v[src].
// ---------------------------------------------------------------------------
__global__ __launch_bounds__(256) void edge_kernel(
    const int* __restrict__ dsts, const int* __restrict__ srcs,
    float* __restrict__ out)
{
    const int e = (blockIdx.x * blockDim.x + threadIdx.x) >> 5;
    const int lane = threadIdx.x & 31;
    if (e >= NEDGES) return;
    const int d = dsts[e];
    const int s = srcs[e];

    const uint2*  qw = reinterpret_cast<const uint2*>(g_qWh + (size_t)d * FEAT * 2);
    const __half* kk = g_kh + (size_t)s * FEAT;

    float ax = 0.f, ay = 0.f, az = 0.f, aw = 0.f;
    #pragma unroll
    for (int it = 0; it < 4; ++it) {
        int f = lane + it * 32;
        if (f < FEAT) {
            float kf = __half2float(kk[f]);
            uint2 wv = qw[f];
            float2 p01 = __half22float2(*reinterpret_cast<__half2*>(&wv.x));
            float2 p23 = __half22float2(*reinterpret_cast<__half2*>(&wv.y));
            ax += p01.x * kf; ay += p01.y * kf; az += p23.x * kf; aw += p23.y * kf;
        }
    }
    #pragma unroll
    for (int off = 16; off > 0; off >>= 1) {
        ax += __shfl_xor_sync(0xffffffffu, ax, off);
        ay += __shfl_xor_sync(0xffffffffu, ay, off);
        az += __shfl_xor_sync(0xffffffffu, az, off);
        aw += __shfl_xor_sync(0xffffffffu, aw, off);
    }
    const float ev = 0.25f * (__expf(ax) + __expf(ay) + __expf(az) + __expf(aw));
    if (lane == 0) atomicAdd(&g_z[d], ev);

    const float w = sqrtf(ev);
    if (lane < FEAT / 4) {  // 30 lanes
        const float4* vv = reinterpret_cast<const float4*>(g_v + (size_t)s * FEAT);
        float4 v4 = vv[lane];
        float* p = out + (size_t)d * FEAT + lane * 4;
        asm volatile("red.global.add.v4.f32 [%0], {%1, %2, %3, %4};"
                     :: "l"(p), "f"(w * v4.x), "f"(w * v4.y), "f"(w * v4.z), "f"(w * v4.w)
                     : "memory");
    }
}

// ---------------------------------------------------------------------------
// Finalize: out = v_node + out * rsqrt(z)   (z==0 -> no edges -> out sum is 0)
// ---------------------------------------------------------------------------
__global__ __launch_bounds__(256) void finalize_kernel(float* __restrict__ out)
{
    const int t = blockIdx.x * blockDim.x + threadIdx.x;
    if (t >= NNODES * (FEAT / 4)) return;
    const int n = t / (FEAT / 4);
    const float zz = g_z[n];
    const float sc = (zz > 0.0f) ? rsqrtf(zz) : 0.0f;
    float4 o = reinterpret_cast<float4*>(out)[t];
    float4 v = reinterpret_cast<const float4*>(g_v)[t];
    o.x = v.x + o.x * sc;
    o.y = v.y + o.y * sc;
    o.z = v.z + o.z * sc;
    o.w = v.w + o.w * sc;
    reinterpret_cast<float4*>(out)[t] = o;
}

// ---------------------------------------------------------------------------
extern "C" void kernel_launch(void* const* d_in, const int* in_sizes, int n_in,
                              void* d_out, int out_size)
{
    const float* x   = (const float*)d_in[0];
    const float* Wq0 = (const float*)d_in[1];
    const float* Wq1 = (const float*)d_in[2];
    const float* Wq2 = (const float*)d_in[3];
    const float* Wk0 = (const float*)d_in[4];
    const float* Wk1 = (const float*)d_in[5];
    const float* Wk2 = (const float*)d_in[6];
    const float* Wv0 = (const float*)d_in[7];
    const float* Wv1 = (const float*)d_in[8];
    const float* Wv2 = (const float*)d_in[9];
    const float* Wd0 = (const float*)d_in[10];
    const float* Wd1 = (const float*)d_in[11];
    const float* Wd2 = (const float*)d_in[12];
    const int* edge_dst = (const int*)d_in[13];
    const int* edge_src = (const int*)d_in[14];
    float* out = (float*)d_out;

    // Node kernel: 40 nodes/block (4 per warp, 10 warps), 50000/40 = 1250 blocks
    node_kernel<<<NNODES / 40, 320>>>(x, Wq0, Wq1, Wq2, Wk0, Wk1, Wk2,
                                      Wv0, Wv1, Wv2, Wd0, Wd1, Wd2, out);

    // Fused edge kernel: 8 edges/block (one warp each)
    edge_kernel<<<(NEDGES + 7) / 8, 256>>>(edge_dst, edge_src, out);

    // Finalize: one thread per float4 of out
    const int nt = NNODES * (FEAT / 4);
    finalize_kernel<<<(nt + 255) / 256, 256>>>(out);
}

// round 13
// speedup vs baseline: 1.0965x; 1.0965x over previous
#include <cuda_runtime.h>
#include <cuda_fp16.h>
#include <math.h>

#define NNODES 50000
#define NEDGES 800000
#define FEAT   120

// Scratch (static __device__ arrays — allocation-free per harness rules)
__device__ __half2 g_qWh[(size_t)NNODES * FEAT * 2]; // [n][f][4 heads as 2x half2], 48 MB
__device__ __half  g_kh [(size_t)NNODES * FEAT];     // 12 MB
__device__ float   g_v  [(size_t)NNODES * FEAT];     // 24 MB (fp32, finalize)
__device__ __half  g_vh [(size_t)NNODES * FEAT];     // 12 MB (fp16, edge gather)
__device__ float   g_z  [NNODES];

__device__ __forceinline__ void store_qw(int n, int f, float4 a, float c) {
    __half2 h01 = __floats2half2_rn(a.x * c, a.y * c);
    __half2 h23 = __floats2half2_rn(a.z * c, a.w * c);
    uint2 u;
    u.x = *reinterpret_cast<unsigned*>(&h01);
    u.y = *reinterpret_cast<unsigned*>(&h23);
    reinterpret_cast<uint2*>(g_qWh)[(size_t)n * FEAT + f] = u;
}

// ---------------------------------------------------------------------------
// Node kernel (R4 verbatim + g_vh store): one warp per 2 nodes, 8 warps/block.
// 50000 = 16 * 3125 exactly -> no bounds checks.
// ---------------------------------------------------------------------------
__global__ __launch_bounds__(256) void node_kernel(
    const float* __restrict__ x,
    const float* __restrict__ Wq0, const float* __restrict__ Wq1, const float* __restrict__ Wq2,
    const float* __restrict__ Wk0, const float* __restrict__ Wk1, const float* __restrict__ Wk2,
    const float* __restrict__ Wv0, const float* __restrict__ Wv1, const float* __restrict__ Wv2,
    const float* __restrict__ Wd0, const float* __restrict__ Wd1, const float* __restrict__ Wd2,
    float* __restrict__ out)
{
    __shared__ float sX[8][2][FEAT];
    __shared__ float sQ[8][2][FEAT];

    const int warp = threadIdx.x >> 5;
    const int lane = threadIdx.x & 31;
    const int n0 = blockIdx.x * 16 + warp * 2;
    const int n1 = n0 + 1;

    float* xs0 = sX[warp][0];
    float* xs1 = sX[warp][1];
    float* qs0 = sQ[warp][0];
    float* qs1 = sQ[warp][1];

    for (int f = lane; f < FEAT; f += 32) {
        xs0[f] = x[(size_t)n0 * FEAT + f];
        xs1[f] = x[(size_t)n1 * FEAT + f];
        out[(size_t)n0 * FEAT + f] = 0.0f;   // out accumulates edge sums
        out[(size_t)n1 * FEAT + f] = 0.0f;
    }
    if (lane == 0) { g_z[n0] = 0.0f; g_z[n1] = 0.0f; }
    __syncwarp();

    const float inv_s32 = 0.1767766953f;   // 1/sqrt(32)
    const float inv_s16 = 0.25f;
    const float inv_s8  = 0.3535533906f;   // 1/sqrt(8)

    __half* kp0 = g_kh + (size_t)n0 * FEAT;
    __half* kp1 = g_kh + (size_t)n1 * FEAT;
    float*  vp0 = g_v  + (size_t)n0 * FEAT;
    float*  vp1 = g_v  + (size_t)n1 * FEAT;
    __half* hp0 = g_vh + (size_t)n0 * FEAT;
    __half* hp1 = g_vh + (size_t)n1 * FEAT;

    #pragma unroll 1
    for (int pass = 0; pass < 3; ++pass) {
        const float* W0 = (pass == 0) ? Wq0 : ((pass == 1) ? Wk0 : Wv0);
        const float* W1 = (pass == 0) ? Wq1 : ((pass == 1) ? Wk1 : Wv1);
        const float* W2 = (pass == 0) ? Wq2 : ((pass == 1) ? Wk2 : Wv2);

        // l=0: output j = lane
        {
            float a0 = 0.f, a1 = 0.f;
            #pragma unroll
            for (int i = 0; i < 32; ++i) {
                float w = __ldg(&W0[i * 32 + lane]);
                a0 += xs0[i] * w;
                a1 += xs1[i] * w;
            }
            a0 *= inv_s32; a1 *= inv_s32;
            float nn0 = sqrtf(a0*a0 + 1e-10f), nn1 = sqrtf(a1*a1 + 1e-10f);
            float y0 = (1.0f / (1.0f + __expf(-nn0))) / nn0 * a0;
            float y1 = (1.0f / (1.0f + __expf(-nn1))) / nn1 * a1;
            if (pass == 0)      { qs0[lane] = y0; qs1[lane] = y1; }
            else if (pass == 1) { kp0[lane] = __float2half_rn(y0); kp1[lane] = __float2half_rn(y1); }
            else { vp0[lane] = y0; vp1[lane] = y1;
                   hp0[lane] = __float2half_rn(y0); hp1[lane] = __float2half_rn(y1); }
        }
        // l=1: lanes 0..15, output j = lane
        if (lane < 16) {
            float r0[3], r1[3];
            #pragma unroll
            for (int m = 0; m < 3; ++m) { r0[m] = 0.f; r1[m] = 0.f; }
            #pragma unroll
            for (int i = 0; i < 16; ++i) {
                float w = __ldg(&W1[i * 16 + lane]);
                #pragma unroll
                for (int m = 0; m < 3; ++m) {
                    r0[m] += xs0[32 + i*3 + m] * w;
                    r1[m] += xs1[32 + i*3 + m] * w;
                }
            }
            float ss0 = 0.f, ss1 = 0.f;
            #pragma unroll
            for (int m = 0; m < 3; ++m) {
                r0[m] *= inv_s16; r1[m] *= inv_s16;
                ss0 += r0[m]*r0[m]; ss1 += r1[m]*r1[m];
            }
            float nn0 = sqrtf(ss0 + 1e-10f), nn1 = sqrtf(ss1 + 1e-10f);
            float sc0 = (1.0f / (1.0f + __expf(-nn0))) / nn0;
            float sc1 = (1.0f / (1.0f + __expf(-nn1))) / nn1;
            #pragma unroll
            for (int m = 0; m < 3; ++m) {
                int f = 32 + lane*3 + m;
                float y0 = sc0 * r0[m], y1 = sc1 * r1[m];
                if (pass == 0)      { qs0[f] = y0; qs1[f] = y1; }
                else if (pass == 1) { kp0[f] = __float2half_rn(y0); kp1[f] = __float2half_rn(y1); }
                else { vp0[f] = y0; vp1[f] = y1;
                       hp0[f] = __float2half_rn(y0); hp1[f] = __float2half_rn(y1); }
            }
        }
        // l=2: lanes 16..23, output j = lane-16
        else if (lane < 24) {
            const int j = lane - 16;
            float r0[5], r1[5];
            #pragma unroll
            for (int m = 0; m < 5; ++m) { r0[m] = 0.f; r1[m] = 0.f; }
            #pragma unroll
            for (int i = 0; i < 8; ++i) {
                float w = __ldg(&W2[i * 8 + j]);
                #pragma unroll
                for (int m = 0; m < 5; ++m) {
                    r0[m] += xs0[80 + i*5 + m] * w;
                    r1[m] += xs1[80 + i*5 + m] * w;
                }
            }
            float ss0 = 0.f, ss1 = 0.f;
            #pragma unroll
            for (int m = 0; m < 5; ++m) {
                r0[m] *= inv_s8; r1[m] *= inv_s8;
                ss0 += r0[m]*r0[m]; ss1 += r1[m]*r1[m];
            }
            float nn0 = sqrtf(ss0 + 1e-10f), nn1 = sqrtf(ss1 + 1e-10f);
            float sc0 = (1.0f / (1.0f + __expf(-nn0))) / nn0;
            float sc1 = (1.0f / (1.0f + __expf(-nn1))) / nn1;
            #pragma unroll
            for (int m = 0; m < 5; ++m) {
                int f = 80 + j*5 + m;
                float y0 = sc0 * r0[m], y1 = sc1 * r1[m];
                if (pass == 0)      { qs0[f] = y0; qs1[f] = y1; }
                else if (pass == 1) { kp0[f] = __float2half_rn(y0); kp1[f] = __float2half_rn(y1); }
                else { vp0[f] = y0; vp1[f] = y1;
                       hp0[f] = __float2half_rn(y0); hp1[f] = __float2half_rn(y1); }
            }
        }
        __syncwarp();
    }

    // ---- Wd contraction: qW[n][f][4], both nodes share every Wd wavefront ----
    const float c0 = 0.02176061898f;     // 1/sqrt(2112)
    const float c1 = c0 * 0.5773502692f; // c0/sqrt(3)
    const float c2 = c0 * 0.4472135955f; // c0/sqrt(5)
    const float4* D0 = reinterpret_cast<const float4*>(Wd0);
    const float4* D1 = reinterpret_cast<const float4*>(Wd1);
    const float4* D2 = reinterpret_cast<const float4*>(Wd2);

    // l=0: j = lane
    {
        float4 A0 = make_float4(0.f,0.f,0.f,0.f);
        float4 A1 = make_float4(0.f,0.f,0.f,0.f);
        #pragma unroll
        for (int i = 0; i < 32; ++i) {
            float4 w = __ldg(&D0[i * 32 + lane]);
            float q0 = qs0[i], q1 = qs1[i];
            A0.x += q0*w.x; A0.y += q0*w.y; A0.z += q0*w.z; A0.w += q0*w.w;
            A1.x += q1*w.x; A1.y += q1*w.y; A1.z += q1*w.z; A1.w += q1*w.w;
        }
        store_qw(n0, lane, A0, c0);
        store_qw(n1, lane, A1, c0);
    }
    // l=1: lanes 0..15, j = lane
    if (lane < 16) {
        float4 B0[3], B1[3];
        #pragma unroll
        for (int m = 0; m < 3; ++m) {
            B0[m] = make_float4(0.f,0.f,0.f,0.f);
            B1[m] = make_float4(0.f,0.f,0.f,0.f);
        }
        #pragma unroll
        for (int i = 0; i < 16; ++i) {
            float4 w = __ldg(&D1[i * 16 + lane]);
            #pragma unroll
            for (int m = 0; m < 3; ++m) {
                float q0 = qs0[32 + i*3 + m], q1 = qs1[32 + i*3 + m];
                B0[m].x += q0*w.x; B0[m].y += q0*w.y; B0[m].z += q0*w.z; B0[m].w += q0*w.w;
                B1[m].x += q1*w.x; B1[m].y += q1*w.y; B1[m].z += q1*w.z; B1[m].w += q1*w.w;
            }
        }
        #pragma unroll
        for (int m = 0; m < 3; ++m) {
            int f = 32 + lane*3 + m;
            store_qw(n0, f, B0[m], c1);
            store_qw(n1, f, B1[m], c1);
        }
    }
    // l=2: lanes 16..23, j = lane-16
    else if (lane < 24) {
        const int j = lane - 16;
        float4 C0[5], C1[5];
        #pragma unroll
        for (int m = 0; m < 5; ++m) {
            C0[m] = make_float4(0.f,0.f,0.f,0.f);
            C1[m] = make_float4(0.f,0.f,0.f,0.f);
        }
        #pragma unroll
        for (int i = 0; i < 8; ++i) {
            float4 w = __ldg(&D2[i * 8 + j]);
            #pragma unroll
            for (int m = 0; m < 5; ++m) {
                float q0 = qs0[80 + i*5 + m], q1 = qs1[80 + i*5 + m];
                C0[m].x += q0*w.x; C0[m].y += q0*w.y; C0[m].z += q0*w.z; C0[m].w += q0*w.w;
                C1[m].x += q1*w.x; C1[m].y += q1*w.y; C1[m].z += q1*w.z; C1[m].w += q1*w.w;
            }
        }
        #pragma unroll
        for (int m = 0; m < 5; ++m) {
            int f = 80 + j*5 + m;
            store_qw(n0, f, C0[m], c2);
            store_qw(n1, f, C1[m], c2);
        }
    }
}

// ---------------------------------------------------------------------------
// Fused edge kernel (R4 lane layout verbatim; ONLY change: v gathered fp16).
// ev = mean_h exp(qW[dst]·k[src]); z[dst] += ev; out[dst] += sqrt(ev)*v[src].
// ---------------------------------------------------------------------------
__global__ __launch_bounds__(256) void edge_kernel(
    const int* __restrict__ dsts, const int* __restrict__ srcs,
    float* __restrict__ out)
{
    const int e = (blockIdx.x * blockDim.x + threadIdx.x) >> 5;
    const int lane = threadIdx.x & 31;
    if (e >= NEDGES) return;
    const int d = dsts[e];
    const int s = srcs[e];

    const uint2*  qw = reinterpret_cast<const uint2*>(g_qWh + (size_t)d * FEAT * 2);
    const __half* kk = g_kh + (size_t)s * FEAT;

    float ax = 0.f, ay = 0.f, az = 0.f, aw = 0.f;
    #pragma unroll
    for (int it = 0; it < 4; ++it) {
        int f = lane + it * 32;
        if (f < FEAT) {
            float kf = __half2float(kk[f]);
            uint2 wv = qw[f];
            float2 p01 = __half22float2(*reinterpret_cast<__half2*>(&wv.x));
            float2 p23 = __half22float2(*reinterpret_cast<__half2*>(&wv.y));
            ax += p01.x * kf; ay += p01.y * kf; az += p23.x * kf; aw += p23.y * kf;
        }
    }
    #pragma unroll
    for (int off = 16; off > 0; off >>= 1) {
        ax += __shfl_xor_sync(0xffffffffu, ax, off);
        ay += __shfl_xor_sync(0xffffffffu, ay, off);
        az += __shfl_xor_sync(0xffffffffu, az, off);
        aw += __shfl_xor_sync(0xffffffffu, aw, off);
    }
    const float ev = 0.25f * (__expf(ax) + __expf(ay) + __expf(az) + __expf(aw));
    if (lane == 0) atomicAdd(&g_z[d], ev);

    const float w = sqrtf(ev);
    if (lane < FEAT / 4) {  // 30 lanes, float4 chunk f = 4*lane (fp16 source)
        uint2 vv = reinterpret_cast<const uint2*>(g_vh + (size_t)s * FEAT)[lane];
        float2 v01 = __half22float2(*reinterpret_cast<__half2*>(&vv.x));
        float2 v23 = __half22float2(*reinterpret_cast<__half2*>(&vv.y));
        float* p = out + (size_t)d * FEAT + lane * 4;
        asm volatile("red.global.add.v4.f32 [%0], {%1, %2, %3, %4};"
                     :: "l"(p), "f"(w * v01.x), "f"(w * v01.y), "f"(w * v23.x), "f"(w * v23.y)
                     : "memory");
    }
}

// ---------------------------------------------------------------------------
// Finalize: out = v_node + out * rsqrt(z)   (z==0 -> no edges -> out sum is 0)
// ---------------------------------------------------------------------------
__global__ __launch_bounds__(256) void finalize_kernel(float* __restrict__ out)
{
    const int t = blockIdx.x * blockDim.x + threadIdx.x;
    if (t >= NNODES * (FEAT / 4)) return;
    const int n = t / (FEAT / 4);
    const float zz = g_z[n];
    const float sc = (zz > 0.0f) ? rsqrtf(zz) : 0.0f;
    float4 o = reinterpret_cast<float4*>(out)[t];
    float4 v = reinterpret_cast<const float4*>(g_v)[t];
    o.x = v.x + o.x * sc;
    o.y = v.y + o.y * sc;
    o.z = v.z + o.z * sc;
    o.w = v.w + o.w * sc;
    reinterpret_cast<float4*>(out)[t] = o;
}

// ---------------------------------------------------------------------------
extern "C" void kernel_launch(void* const* d_in, const int* in_sizes, int n_in,
                              void* d_out, int out_size)
{
    const float* x   = (const float*)d_in[0];
    const float* Wq0 = (const float*)d_in[1];
    const float* Wq1 = (const float*)d_in[2];
    const float* Wq2 = (const float*)d_in[3];
    const float* Wk0 = (const float*)d_in[4];
    const float* Wk1 = (const float*)d_in[5];
    const float* Wk2 = (const float*)d_in[6];
    const float* Wv0 = (const float*)d_in[7];
    const float* Wv1 = (const float*)d_in[8];
    const float* Wv2 = (const float*)d_in[9];
    const float* Wd0 = (const float*)d_in[10];
    const float* Wd1 = (const float*)d_in[11];
    const float* Wd2 = (const float*)d_in[12];
    const int* edge_dst = (const int*)d_in[13];
    const int* edge_src = (const int*)d_in[14];
    float* out = (float*)d_out;

    // Node kernel: 16 nodes/block (2 per warp), 50000/16 = 3125 blocks
    node_kernel<<<NNODES / 16, 256>>>(x, Wq0, Wq1, Wq2, Wk0, Wk1, Wk2,
                                      Wv0, Wv1, Wv2, Wd0, Wd1, Wd2, out);

    // Fused edge kernel: 8 edges/block (one warp each)
    edge_kernel<<<(NEDGES + 7) / 8, 256>>>(edge_dst, edge_src, out);

    // Finalize: one thread per float4 of out
    const int nt = NNODES * (FEAT / 4);
    finalize_kernel<<<(nt + 255) / 256, 256>>>(out);
}

// round 14
// speedup vs baseline: 1.1259x; 1.0268x over previous
#include <cuda_runtime.h>
#include <cuda_fp16.h>
#include <math.h>

#define NNODES 50000
#define NEDGES 800000
#define FEAT   120

// Scratch (static __device__ arrays — allocation-free per harness rules)
__device__ __half2 g_qWh[(size_t)NNODES * FEAT * 2]; // [n][f][4 heads as 2x half2], 48 MB
__device__ __half  g_kh [(size_t)NNODES * FEAT];     // 12 MB
__device__ float   g_v  [(size_t)NNODES * FEAT];     // 24 MB (fp32, finalize)
__device__ __half  g_vh [(size_t)NNODES * FEAT];     // 12 MB (fp16, edge gather)
__device__ float   g_z  [NNODES];

__device__ __forceinline__ void store_qw(int n, int f, float4 a, float c) {
    __half2 h01 = __floats2half2_rn(a.x * c, a.y * c);
    __half2 h23 = __floats2half2_rn(a.z * c, a.w * c);
    uint2 u;
    u.x = *reinterpret_cast<unsigned*>(&h01);
    u.y = *reinterpret_cast<unsigned*>(&h23);
    reinterpret_cast<uint2*>(g_qWh)[(size_t)n * FEAT + f] = u;
}

// ---------------------------------------------------------------------------
// Node kernel (R4 VERBATIM — do not touch): one warp per 2 nodes, 8 warps/blk.
// 50000 = 16 * 3125 exactly -> no bounds checks.
// ---------------------------------------------------------------------------
__global__ __launch_bounds__(256) void node_kernel(
    const float* __restrict__ x,
    const float* __restrict__ Wq0, const float* __restrict__ Wq1, const float* __restrict__ Wq2,
    const float* __restrict__ Wk0, const float* __restrict__ Wk1, const float* __restrict__ Wk2,
    const float* __restrict__ Wv0, const float* __restrict__ Wv1, const float* __restrict__ Wv2,
    const float* __restrict__ Wd0, const float* __restrict__ Wd1, const float* __restrict__ Wd2,
    float* __restrict__ out)
{
    __shared__ float sX[8][2][FEAT];
    __shared__ float sQ[8][2][FEAT];

    const int warp = threadIdx.x >> 5;
    const int lane = threadIdx.x & 31;
    const int n0 = blockIdx.x * 16 + warp * 2;
    const int n1 = n0 + 1;

    float* xs0 = sX[warp][0];
    float* xs1 = sX[warp][1];
    float* qs0 = sQ[warp][0];
    float* qs1 = sQ[warp][1];

    for (int f = lane; f < FEAT; f += 32) {
        xs0[f] = x[(size_t)n0 * FEAT + f];
        xs1[f] = x[(size_t)n1 * FEAT + f];
        out[(size_t)n0 * FEAT + f] = 0.0f;   // out accumulates edge sums
        out[(size_t)n1 * FEAT + f] = 0.0f;
    }
    if (lane == 0) { g_z[n0] = 0.0f; g_z[n1] = 0.0f; }
    __syncwarp();

    const float inv_s32 = 0.1767766953f;   // 1/sqrt(32)
    const float inv_s16 = 0.25f;
    const float inv_s8  = 0.3535533906f;   // 1/sqrt(8)

    __half* kp0 = g_kh + (size_t)n0 * FEAT;
    __half* kp1 = g_kh + (size_t)n1 * FEAT;
    float*  vp0 = g_v  + (size_t)n0 * FEAT;
    float*  vp1 = g_v  + (size_t)n1 * FEAT;

    #pragma unroll 1
    for (int pass = 0; pass < 3; ++pass) {
        const float* W0 = (pass == 0) ? Wq0 : ((pass == 1) ? Wk0 : Wv0);
        const float* W1 = (pass == 0) ? Wq1 : ((pass == 1) ? Wk1 : Wv1);
        const float* W2 = (pass == 0) ? Wq2 : ((pass == 1) ? Wk2 : Wv2);

        // l=0: output j = lane
        {
            float a0 = 0.f, a1 = 0.f;
            #pragma unroll
            for (int i = 0; i < 32; ++i) {
                float w = __ldg(&W0[i * 32 + lane]);
                a0 += xs0[i] * w;
                a1 += xs1[i] * w;
            }
            a0 *= inv_s32; a1 *= inv_s32;
            float nn0 = sqrtf(a0*a0 + 1e-10f), nn1 = sqrtf(a1*a1 + 1e-10f);
            float y0 = (1.0f / (1.0f + __expf(-nn0))) / nn0 * a0;
            float y1 = (1.0f / (1.0f + __expf(-nn1))) / nn1 * a1;
            if (pass == 0)      { qs0[lane] = y0; qs1[lane] = y1; }
            else if (pass == 1) { kp0[lane] = __float2half_rn(y0); kp1[lane] = __float2half_rn(y1); }
            else                { vp0[lane] = y0; vp1[lane] = y1; }
        }
        // l=1: lanes 0..15, output j = lane
        if (lane < 16) {
            float r0[3], r1[3];
            #pragma unroll
            for (int m = 0; m < 3; ++m) { r0[m] = 0.f; r1[m] = 0.f; }
            #pragma unroll
            for (int i = 0; i < 16; ++i) {
                float w = __ldg(&W1[i * 16 + lane]);
                #pragma unroll
                for (int m = 0; m < 3; ++m) {
                    r0[m] += xs0[32 + i*3 + m] * w;
                    r1[m] += xs1[32 + i*3 + m] * w;
                }
            }
            float ss0 = 0.f, ss1 = 0.f;
            #pragma unroll
            for (int m = 0; m < 3; ++m) {
                r0[m] *= inv_s16; r1[m] *= inv_s16;
                ss0 += r0[m]*r0[m]; ss1 += r1[m]*r1[m];
            }
            float nn0 = sqrtf(ss0 + 1e-10f), nn1 = sqrtf(ss1 + 1e-10f);
            float sc0 = (1.0f / (1.0f + __expf(-nn0))) / nn0;
            float sc1 = (1.0f / (1.0f + __expf(-nn1))) / nn1;
            #pragma unroll
            for (int m = 0; m < 3; ++m) {
                int f = 32 + lane*3 + m;
                float y0 = sc0 * r0[m], y1 = sc1 * r1[m];
                if (pass == 0)      { qs0[f] = y0; qs1[f] = y1; }
                else if (pass == 1) { kp0[f] = __float2half_rn(y0); kp1[f] = __float2half_rn(y1); }
                else                { vp0[f] = y0; vp1[f] = y1; }
            }
        }
        // l=2: lanes 16..23, output j = lane-16
        else if (lane < 24) {
            const int j = lane - 16;
            float r0[5], r1[5];
            #pragma unroll
            for (int m = 0; m < 5; ++m) { r0[m] = 0.f; r1[m] = 0.f; }
            #pragma unroll
            for (int i = 0; i < 8; ++i) {
                float w = __ldg(&W2[i * 8 + j]);
                #pragma unroll
                for (int m = 0; m < 5; ++m) {
                    r0[m] += xs0[80 + i*5 + m] * w;
                    r1[m] += xs1[80 + i*5 + m] * w;
                }
            }
            float ss0 = 0.f, ss1 = 0.f;
            #pragma unroll
            for (int m = 0; m < 5; ++m) {
                r0[m] *= inv_s8; r1[m] *= inv_s8;
                ss0 += r0[m]*r0[m]; ss1 += r1[m]*r1[m];
            }
            float nn0 = sqrtf(ss0 + 1e-10f), nn1 = sqrtf(ss1 + 1e-10f);
            float sc0 = (1.0f / (1.0f + __expf(-nn0))) / nn0;
            float sc1 = (1.0f / (1.0f + __expf(-nn1))) / nn1;
            #pragma unroll
            for (int m = 0; m < 5; ++m) {
                int f = 80 + j*5 + m;
                float y0 = sc0 * r0[m], y1 = sc1 * r1[m];
                if (pass == 0)      { qs0[f] = y0; qs1[f] = y1; }
                else if (pass == 1) { kp0[f] = __float2half_rn(y0); kp1[f] = __float2half_rn(y1); }
                else                { vp0[f] = y0; vp1[f] = y1; }
            }
        }
        __syncwarp();
    }

    // ---- Wd contraction: qW[n][f][4], both nodes share every Wd wavefront ----
    const float c0 = 0.02176061898f;     // 1/sqrt(2112)
    const float c1 = c0 * 0.5773502692f; // c0/sqrt(3)
    const float c2 = c0 * 0.4472135955f; // c0/sqrt(5)
    const float4* D0 = reinterpret_cast<const float4*>(Wd0);
    const float4* D1 = reinterpret_cast<const float4*>(Wd1);
    const float4* D2 = reinterpret_cast<const float4*>(Wd2);

    // l=0: j = lane
    {
        float4 A0 = make_float4(0.f,0.f,0.f,0.f);
        float4 A1 = make_float4(0.f,0.f,0.f,0.f);
        #pragma unroll
        for (int i = 0; i < 32; ++i) {
            float4 w = __ldg(&D0[i * 32 + lane]);
            float q0 = qs0[i], q1 = qs1[i];
            A0.x += q0*w.x; A0.y += q0*w.y; A0.z += q0*w.z; A0.w += q0*w.w;
            A1.x += q1*w.x; A1.y += q1*w.y; A1.z += q1*w.z; A1.w += q1*w.w;
        }
        store_qw(n0, lane, A0, c0);
        store_qw(n1, lane, A1, c0);
    }
    // l=1: lanes 0..15, j = lane
    if (lane < 16) {
        float4 B0[3], B1[3];
        #pragma unroll
        for (int m = 0; m < 3; ++m) {
            B0[m] = make_float4(0.f,0.f,0.f,0.f);
            B1[m] = make_float4(0.f,0.f,0.f,0.f);
        }
        #pragma unroll
        for (int i = 0; i < 16; ++i) {
            float4 w = __ldg(&D1[i * 16 + lane]);
            #pragma unroll
            for (int m = 0; m < 3; ++m) {
                float q0 = qs0[32 + i*3 + m], q1 = qs1[32 + i*3 + m];
                B0[m].x += q0*w.x; B0[m].y += q0*w.y; B0[m].z += q0*w.z; B0[m].w += q0*w.w;
                B1[m].x += q1*w.x; B1[m].y += q1*w.y; B1[m].z += q1*w.z; B1[m].w += q1*w.w;
            }
        }
        #pragma unroll
        for (int m = 0; m < 3; ++m) {
            int f = 32 + lane*3 + m;
            store_qw(n0, f, B0[m], c1);
            store_qw(n1, f, B1[m], c1);
        }
    }
    // l=2: lanes 16..23, j = lane-16
    else if (lane < 24) {
        const int j = lane - 16;
        float4 C0[5], C1[5];
        #pragma unroll
        for (int m = 0; m < 5; ++m) {
            C0[m] = make_float4(0.f,0.f,0.f,0.f);
            C1[m] = make_float4(0.f,0.f,0.f,0.f);
        }
        #pragma unroll
        for (int i = 0; i < 8; ++i) {
            float4 w = __ldg(&D2[i * 8 + j]);
            #pragma unroll
            for (int m = 0; m < 5; ++m) {
                float q0 = qs0[80 + i*5 + m], q1 = qs1[80 + i*5 + m];
                C0[m].x += q0*w.x; C0[m].y += q0*w.y; C0[m].z += q0*w.z; C0[m].w += q0*w.w;
                C1[m].x += q1*w.x; C1[m].y += q1*w.y; C1[m].z += q1*w.z; C1[m].w += q1*w.w;
            }
        }
        #pragma unroll
        for (int m = 0; m < 5; ++m) {
            int f = 80 + j*5 + m;
            store_qw(n0, f, C0[m], c2);
            store_qw(n1, f, C1[m], c2);
        }
    }
}

// ---------------------------------------------------------------------------
// Convert kernel: g_vh = fp16(g_v). Trivial, bandwidth-only (~36 MB).
// ---------------------------------------------------------------------------
__global__ __launch_bounds__(256) void convert_v_kernel()
{
    const int t = blockIdx.x * blockDim.x + threadIdx.x;
    if (t < NNODES * (FEAT / 2)) {
        float2 v = reinterpret_cast<const float2*>(g_v)[t];
        reinterpret_cast<__half2*>(g_vh)[t] = __floats2half2_rn(v.x, v.y);
    }
}

// ---------------------------------------------------------------------------
// Fused edge kernel (R4 lane layout; v gathered fp16): one warp per edge.
// ev = mean_h exp(qW[dst]·k[src]); z[dst] += ev; out[dst] += sqrt(ev)*v[src].
// ---------------------------------------------------------------------------
__global__ __launch_bounds__(256) void edge_kernel(
    const int* __restrict__ dsts, const int* __restrict__ srcs,
    float* __restrict__ out)
{
    const int e = (blockIdx.x * blockDim.x + threadIdx.x) >> 5;
    const int lane = threadIdx.x & 31;
    if (e >= NEDGES) return;
    const int d = dsts[e];
    const int s = srcs[e];

    const uint2*  qw = reinterpret_cast<const uint2*>(g_qWh + (size_t)d * FEAT * 2);
    const __half* kk = g_kh + (size_t)s * FEAT;

    float ax = 0.f, ay = 0.f, az = 0.f, aw = 0.f;
    #pragma unroll
    for (int it = 0; it < 4; ++it) {
        int f = lane + it * 32;
        if (f < FEAT) {
            float kf = __half2float(kk[f]);
            uint2 wv = qw[f];
            float2 p01 = __half22float2(*reinterpret_cast<__half2*>(&wv.x));
            float2 p23 = __half22float2(*reinterpret_cast<__half2*>(&wv.y));
            ax += p01.x * kf; ay += p01.y * kf; az += p23.x * kf; aw += p23.y * kf;
        }
    }
    #pragma unroll
    for (int off = 16; off > 0; off >>= 1) {
        ax += __shfl_xor_sync(0xffffffffu, ax, off);
        ay += __shfl_xor_sync(0xffffffffu, ay, off);
        az += __shfl_xor_sync(0xffffffffu, az, off);
        aw += __shfl_xor_sync(0xffffffffu, aw, off);
    }
    const float ev = 0.25f * (__expf(ax) + __expf(ay) + __expf(az) + __expf(aw));
    if (lane == 0) atomicAdd(&g_z[d], ev);

    const float w = sqrtf(ev);
    if (lane < FEAT / 4) {  // 30 lanes, float4 chunk f = 4*lane (fp16 source)
        uint2 vv = reinterpret_cast<const uint2*>(g_vh + (size_t)s * FEAT)[lane];
        float2 v01 = __half22float2(*reinterpret_cast<__half2*>(&vv.x));
        float2 v23 = __half22float2(*reinterpret_cast<__half2*>(&vv.y));
        float* p = out + (size_t)d * FEAT + lane * 4;
        asm volatile("red.global.add.v4.f32 [%0], {%1, %2, %3, %4};"
                     :: "l"(p), "f"(w * v01.x), "f"(w * v01.y), "f"(w * v23.x), "f"(w * v23.y)
                     : "memory");
    }
}

// ---------------------------------------------------------------------------
// Finalize: out = v_node + out * rsqrt(z)   (z==0 -> no edges -> out sum is 0)
// ---------------------------------------------------------------------------
__global__ __launch_bounds__(256) void finalize_kernel(float* __restrict__ out)
{
    const int t = blockIdx.x * blockDim.x + threadIdx.x;
    if (t >= NNODES * (FEAT / 4)) return;
    const int n = t / (FEAT / 4);
    const float zz = g_z[n];
    const float sc = (zz > 0.0f) ? rsqrtf(zz) : 0.0f;
    float4 o = reinterpret_cast<float4*>(out)[t];
    float4 v = reinterpret_cast<const float4*>(g_v)[t];
    o.x = v.x + o.x * sc;
    o.y = v.y + o.y * sc;
    o.z = v.z + o.z * sc;
    o.w = v.w + o.w * sc;
    reinterpret_cast<float4*>(out)[t] = o;
}

// ---------------------------------------------------------------------------
extern "C" void kernel_launch(void* const* d_in, const int* in_sizes, int n_in,
                              void* d_out, int out_size)
{
    const float* x   = (const float*)d_in[0];
    const float* Wq0 = (const float*)d_in[1];
    const float* Wq1 = (const float*)d_in[2];
    const float* Wq2 = (const float*)d_in[3];
    const float* Wk0 = (const float*)d_in[4];
    const float* Wk1 = (const float*)d_in[5];
    const float* Wk2 = (const float*)d_in[6];
    const float* Wv0 = (const float*)d_in[7];
    const float* Wv1 = (const float*)d_in[8];
    const float* Wv2 = (const float*)d_in[9];
    const float* Wd0 = (const float*)d_in[10];
    const float* Wd1 = (const float*)d_in[11];
    const float* Wd2 = (const float*)d_in[12];
    const int* edge_dst = (const int*)d_in[13];
    const int* edge_src = (const int*)d_in[14];
    float* out = (float*)d_out;

    // Node kernel: 16 nodes/block (2 per warp), 50000/16 = 3125 blocks
    node_kernel<<<NNODES / 16, 256>>>(x, Wq0, Wq1, Wq2, Wk0, Wk1, Wk2,
                                      Wv0, Wv1, Wv2, Wd0, Wd1, Wd2, out);

    // Convert v to fp16 for the edge gather (separate kernel: keeps node lean)
    const int nc = NNODES * (FEAT / 2);
    convert_v_kernel<<<(nc + 255) / 256, 256>>>();

    // Fused edge kernel: 8 edges/block (one warp each)
    edge_kernel<<<(NEDGES + 7) / 8, 256>>>(edge_dst, edge_src, out);

    // Finalize: one thread per float4 of out
    const int nt = NNODES * (FEAT / 4);
    finalize_kernel<<<(nt + 255) / 256, 256>>>(out);
}

// round 15
// speedup vs baseline: 1.1637x; 1.0336x over previous
#include <cuda_runtime.h>
#include <cuda_fp16.h>
#include <math.h>

#define NNODES 50000
#define NEDGES 800000
#define FEAT   120

// Scratch (static __device__ arrays — allocation-free per harness rules)
__device__ __half2 g_qWh[(size_t)NNODES * FEAT * 2]; // [n][f][4 heads as 2x half2], 48 MB
__device__ __half  g_kh [(size_t)NNODES * FEAT];     // 12 MB
__device__ __half  g_vh [(size_t)NNODES * FEAT];     // 12 MB (fp16 v, edge gather + finalize)
__device__ float   g_z  [NNODES];

__device__ __forceinline__ void store_qw(int n, int f, float4 a, float c) {
    __half2 h01 = __floats2half2_rn(a.x * c, a.y * c);
    __half2 h23 = __floats2half2_rn(a.z * c, a.w * c);
    uint2 u;
    u.x = *reinterpret_cast<unsigned*>(&h01);
    u.y = *reinterpret_cast<unsigned*>(&h23);
    reinterpret_cast<uint2*>(g_qWh)[(size_t)n * FEAT + f] = u;
}

// ---------------------------------------------------------------------------
// Node kernel (R4 shape; pass-2 v store is fp16 instead of fp32 — same
// instruction count): one warp per 2 nodes, 8 warps/block.
// 50000 = 16 * 3125 exactly -> no bounds checks.
// ---------------------------------------------------------------------------
__global__ __launch_bounds__(256) void node_kernel(
    const float* __restrict__ x,
    const float* __restrict__ Wq0, const float* __restrict__ Wq1, const float* __restrict__ Wq2,
    const float* __restrict__ Wk0, const float* __restrict__ Wk1, const float* __restrict__ Wk2,
    const float* __restrict__ Wv0, const float* __restrict__ Wv1, const float* __restrict__ Wv2,
    const float* __restrict__ Wd0, const float* __restrict__ Wd1, const float* __restrict__ Wd2,
    float* __restrict__ out)
{
    __shared__ float sX[8][2][FEAT];
    __shared__ float sQ[8][2][FEAT];

    const int warp = threadIdx.x >> 5;
    const int lane = threadIdx.x & 31;
    const int n0 = blockIdx.x * 16 + warp * 2;
    const int n1 = n0 + 1;

    float* xs0 = sX[warp][0];
    float* xs1 = sX[warp][1];
    float* qs0 = sQ[warp][0];
    float* qs1 = sQ[warp][1];

    for (int f = lane; f < FEAT; f += 32) {
        xs0[f] = x[(size_t)n0 * FEAT + f];
        xs1[f] = x[(size_t)n1 * FEAT + f];
        out[(size_t)n0 * FEAT + f] = 0.0f;   // out accumulates edge sums
        out[(size_t)n1 * FEAT + f] = 0.0f;
    }
    if (lane == 0) { g_z[n0] = 0.0f; g_z[n1] = 0.0f; }
    __syncwarp();

    const float inv_s32 = 0.1767766953f;   // 1/sqrt(32)
    const float inv_s16 = 0.25f;
    const float inv_s8  = 0.3535533906f;   // 1/sqrt(8)

    __half* kp0 = g_kh + (size_t)n0 * FEAT;
    __half* kp1 = g_kh + (size_t)n1 * FEAT;
    __half* vp0 = g_vh + (size_t)n0 * FEAT;
    __half* vp1 = g_vh + (size_t)n1 * FEAT;

    #pragma unroll 1
    for (int pass = 0; pass < 3; ++pass) {
        const float* W0 = (pass == 0) ? Wq0 : ((pass == 1) ? Wk0 : Wv0);
        const float* W1 = (pass == 0) ? Wq1 : ((pass == 1) ? Wk1 : Wv1);
        const float* W2 = (pass == 0) ? Wq2 : ((pass == 1) ? Wk2 : Wv2);

        // l=0: output j = lane
        {
            float a0 = 0.f, a1 = 0.f;
            #pragma unroll
            for (int i = 0; i < 32; ++i) {
                float w = __ldg(&W0[i * 32 + lane]);
                a0 += xs0[i] * w;
                a1 += xs1[i] * w;
            }
            a0 *= inv_s32; a1 *= inv_s32;
            float nn0 = sqrtf(a0*a0 + 1e-10f), nn1 = sqrtf(a1*a1 + 1e-10f);
            float y0 = (1.0f / (1.0f + __expf(-nn0))) / nn0 * a0;
            float y1 = (1.0f / (1.0f + __expf(-nn1))) / nn1 * a1;
            if (pass == 0)      { qs0[lane] = y0; qs1[lane] = y1; }
            else if (pass == 1) { kp0[lane] = __float2half_rn(y0); kp1[lane] = __float2half_rn(y1); }
            else                { vp0[lane] = __float2half_rn(y0); vp1[lane] = __float2half_rn(y1); }
        }
        // l=1: lanes 0..15, output j = lane
        if (lane < 16) {
            float r0[3], r1[3];
            #pragma unroll
            for (int m = 0; m < 3; ++m) { r0[m] = 0.f; r1[m] = 0.f; }
            #pragma unroll
            for (int i = 0; i < 16; ++i) {
                float w = __ldg(&W1[i * 16 + lane]);
                #pragma unroll
                for (int m = 0; m < 3; ++m) {
                    r0[m] += xs0[32 + i*3 + m] * w;
                    r1[m] += xs1[32 + i*3 + m] * w;
                }
            }
            float ss0 = 0.f, ss1 = 0.f;
            #pragma unroll
            for (int m = 0; m < 3; ++m) {
                r0[m] *= inv_s16; r1[m] *= inv_s16;
                ss0 += r0[m]*r0[m]; ss1 += r1[m]*r1[m];
            }
            float nn0 = sqrtf(ss0 + 1e-10f), nn1 = sqrtf(ss1 + 1e-10f);
            float sc0 = (1.0f / (1.0f + __expf(-nn0))) / nn0;
            float sc1 = (1.0f / (1.0f + __expf(-nn1))) / nn1;
            #pragma unroll
            for (int m = 0; m < 3; ++m) {
                int f = 32 + lane*3 + m;
                float y0 = sc0 * r0[m], y1 = sc1 * r1[m];
                if (pass == 0)      { qs0[f] = y0; qs1[f] = y1; }
                else if (pass == 1) { kp0[f] = __float2half_rn(y0); kp1[f] = __float2half_rn(y1); }
                else                { vp0[f] = __float2half_rn(y0); vp1[f] = __float2half_rn(y1); }
            }
        }
        // l=2: lanes 16..23, output j = lane-16
        else if (lane < 24) {
            const int j = lane - 16;
            float r0[5], r1[5];
            #pragma unroll
            for (int m = 0; m < 5; ++m) { r0[m] = 0.f; r1[m] = 0.f; }
            #pragma unroll
            for (int i = 0; i < 8; ++i) {
                float w = __ldg(&W2[i * 8 + j]);
                #pragma unroll
                for (int m = 0; m < 5; ++m) {
                    r0[m] += xs0[80 + i*5 + m] * w;
                    r1[m] += xs1[80 + i*5 + m] * w;
                }
            }
            float ss0 = 0.f, ss1 = 0.f;
            #pragma unroll
            for (int m = 0; m < 5; ++m) {
                r0[m] *= inv_s8; r1[m] *= inv_s8;
                ss0 += r0[m]*r0[m]; ss1 += r1[m]*r1[m];
            }
            float nn0 = sqrtf(ss0 + 1e-10f), nn1 = sqrtf(ss1 + 1e-10f);
            float sc0 = (1.0f / (1.0f + __expf(-nn0))) / nn0;
            float sc1 = (1.0f / (1.0f + __expf(-nn1))) / nn1;
            #pragma unroll
            for (int m = 0; m < 5; ++m) {
                int f = 80 + j*5 + m;
                float y0 = sc0 * r0[m], y1 = sc1 * r1[m];
                if (pass == 0)      { qs0[f] = y0; qs1[f] = y1; }
                else if (pass == 1) { kp0[f] = __float2half_rn(y0); kp1[f] = __float2half_rn(y1); }
                else                { vp0[f] = __float2half_rn(y0); vp1[f] = __float2half_rn(y1); }
            }
        }
        __syncwarp();
    }

    // ---- Wd contraction: qW[n][f][4], both nodes share every Wd wavefront ----
    const float c0 = 0.02176061898f;     // 1/sqrt(2112)
    const float c1 = c0 * 0.5773502692f; // c0/sqrt(3)
    const float c2 = c0 * 0.4472135955f; // c0/sqrt(5)
    const float4* D0 = reinterpret_cast<const float4*>(Wd0);
    const float4* D1 = reinterpret_cast<const float4*>(Wd1);
    const float4* D2 = reinterpret_cast<const float4*>(Wd2);

    // l=0: j = lane
    {
        float4 A0 = make_float4(0.f,0.f,0.f,0.f);
        float4 A1 = make_float4(0.f,0.f,0.f,0.f);
        #pragma unroll
        for (int i = 0; i < 32; ++i) {
            float4 w = __ldg(&D0[i * 32 + lane]);
            float q0 = qs0[i], q1 = qs1[i];
            A0.x += q0*w.x; A0.y += q0*w.y; A0.z += q0*w.z; A0.w += q0*w.w;
            A1.x += q1*w.x; A1.y += q1*w.y; A1.z += q1*w.z; A1.w += q1*w.w;
        }
        store_qw(n0, lane, A0, c0);
        store_qw(n1, lane, A1, c0);
    }
    // l=1: lanes 0..15, j = lane
    if (lane < 16) {
        float4 B0[3], B1[3];
        #pragma unroll
        for (int m = 0; m < 3; ++m) {
            B0[m] = make_float4(0.f,0.f,0.f,0.f);
            B1[m] = make_float4(0.f,0.f,0.f,0.f);
        }
        #pragma unroll
        for (int i = 0; i < 16; ++i) {
            float4 w = __ldg(&D1[i * 16 + lane]);
            #pragma unroll
            for (int m = 0; m < 3; ++m) {
                float q0 = qs0[32 + i*3 + m], q1 = qs1[32 + i*3 + m];
                B0[m].x += q0*w.x; B0[m].y += q0*w.y; B0[m].z += q0*w.z; B0[m].w += q0*w.w;
                B1[m].x += q1*w.x; B1[m].y += q1*w.y; B1[m].z += q1*w.z; B1[m].w += q1*w.w;
            }
        }
        #pragma unroll
        for (int m = 0; m < 3; ++m) {
            int f = 32 + lane*3 + m;
            store_qw(n0, f, B0[m], c1);
            store_qw(n1, f, B1[m], c1);
        }
    }
    // l=2: lanes 16..23, j = lane-16
    else if (lane < 24) {
        const int j = lane - 16;
        float4 C0[5], C1[5];
        #pragma unroll
        for (int m = 0; m < 5; ++m) {
            C0[m] = make_float4(0.f,0.f,0.f,0.f);
            C1[m] = make_float4(0.f,0.f,0.f,0.f);
        }
        #pragma unroll
        for (int i = 0; i < 8; ++i) {
            float4 w = __ldg(&D2[i * 8 + j]);
            #pragma unroll
            for (int m = 0; m < 5; ++m) {
                float q0 = qs0[80 + i*5 + m], q1 = qs1[80 + i*5 + m];
                C0[m].x += q0*w.x; C0[m].y += q0*w.y; C0[m].z += q0*w.z; C0[m].w += q0*w.w;
                C1[m].x += q1*w.x; C1[m].y += q1*w.y; C1[m].z += q1*w.z; C1[m].w += q1*w.w;
            }
        }
        #pragma unroll
        for (int m = 0; m < 5; ++m) {
            int f = 80 + j*5 + m;
            store_qw(n0, f, C0[m], c2);
            store_qw(n1, f, C1[m], c2);
        }
    }
}

// ---------------------------------------------------------------------------
// Fused edge kernel (R14 verbatim): one warp per edge, v gathered fp16.
// ev = mean_h exp(qW[dst]·k[src]); z[dst] += ev; out[dst] += sqrt(ev)*v[src].
// ---------------------------------------------------------------------------
__global__ __launch_bounds__(256) void edge_kernel(
    const int* __restrict__ dsts, const int* __restrict__ srcs,
    float* __restrict__ out)
{
    const int e = (blockIdx.x * blockDim.x + threadIdx.x) >> 5;
    const int lane = threadIdx.x & 31;
    if (e >= NEDGES) return;
    const int d = dsts[e];
    const int s = srcs[e];

    const uint2*  qw = reinterpret_cast<const uint2*>(g_qWh + (size_t)d * FEAT * 2);
    const __half* kk = g_kh + (size_t)s * FEAT;

    float ax = 0.f, ay = 0.f, az = 0.f, aw = 0.f;
    #pragma unroll
    for (int it = 0; it < 4; ++it) {
        int f = lane + it * 32;
        if (f < FEAT) {
            float kf = __half2float(kk[f]);
            uint2 wv = qw[f];
            float2 p01 = __half22float2(*reinterpret_cast<__half2*>(&wv.x));
            float2 p23 = __half22float2(*reinterpret_cast<__half2*>(&wv.y));
            ax += p01.x * kf; ay += p01.y * kf; az += p23.x * kf; aw += p23.y * kf;
        }
    }
    #pragma unroll
    for (int off = 16; off > 0; off >>= 1) {
        ax += __shfl_xor_sync(0xffffffffu, ax, off);
        ay += __shfl_xor_sync(0xffffffffu, ay, off);
        az += __shfl_xor_sync(0xffffffffu, az, off);
        aw += __shfl_xor_sync(0xffffffffu, aw, off);
    }
    const float ev = 0.25f * (__expf(ax) + __expf(ay) + __expf(az) + __expf(aw));
    if (lane == 0) atomicAdd(&g_z[d], ev);

    const float w = sqrtf(ev);
    if (lane < FEAT / 4) {  // 30 lanes, float4 chunk f = 4*lane (fp16 source)
        uint2 vv = reinterpret_cast<const uint2*>(g_vh + (size_t)s * FEAT)[lane];
        float2 v01 = __half22float2(*reinterpret_cast<__half2*>(&vv.x));
        float2 v23 = __half22float2(*reinterpret_cast<__half2*>(&vv.y));
        float* p = out + (size_t)d * FEAT + lane * 4;
        asm volatile("red.global.add.v4.f32 [%0], {%1, %2, %3, %4};"
                     :: "l"(p), "f"(w * v01.x), "f"(w * v01.y), "f"(w * v23.x), "f"(w * v23.y)
                     : "memory");
    }
}

// ---------------------------------------------------------------------------
// Finalize: out = v_node(fp16) + out * rsqrt(z)   (z==0 -> out sum is 0)
// ---------------------------------------------------------------------------
__global__ __launch_bounds__(256) void finalize_kernel(float* __restrict__ out)
{
    const int t = blockIdx.x * blockDim.x + threadIdx.x;
    if (t >= NNODES * (FEAT / 4)) return;
    const int n = t / (FEAT / 4);
    const float zz = g_z[n];
    const float sc = (zz > 0.0f) ? rsqrtf(zz) : 0.0f;
    float4 o = reinterpret_cast<float4*>(out)[t];
    uint2 vv = reinterpret_cast<const uint2*>(g_vh)[t];
    float2 v01 = __half22float2(*reinterpret_cast<__half2*>(&vv.x));
    float2 v23 = __half22float2(*reinterpret_cast<__half2*>(&vv.y));
    o.x = v01.x + o.x * sc;
    o.y = v01.y + o.y * sc;
    o.z = v23.x + o.z * sc;
    o.w = v23.y + o.w * sc;
    reinterpret_cast<float4*>(out)[t] = o;
}

// ---------------------------------------------------------------------------
extern "C" void kernel_launch(void* const* d_in, const int* in_sizes, int n_in,
                              void* d_out, int out_size)
{
    const float* x   = (const float*)d_in[0];
    const float* Wq0 = (const float*)d_in[1];
    const float* Wq1 = (const float*)d_in[2];
    const float* Wq2 = (const float*)d_in[3];
    const float* Wk0 = (const float*)d_in[4];
    const float* Wk1 = (const float*)d_in[5];
    const float* Wk2 = (const float*)d_in[6];
    const float* Wv0 = (const float*)d_in[7];
    const float* Wv1 = (const float*)d_in[8];
    const float* Wv2 = (const float*)d_in[9];
    const float* Wd0 = (const float*)d_in[10];
    const float* Wd1 = (const float*)d_in[11];
    const float* Wd2 = (const float*)d_in[12];
    const int* edge_dst = (const int*)d_in[13];
    const int* edge_src = (const int*)d_in[14];
    float* out = (float*)d_out;

    // Node kernel: 16 nodes/block (2 per warp), 50000/16 = 3125 blocks
    node_kernel<<<NNODES / 16, 256>>>(x, Wq0, Wq1, Wq2, Wk0, Wk1, Wk2,
                                      Wv0, Wv1, Wv2, Wd0, Wd1, Wd2, out);

    // Fused edge kernel: 8 edges/block (one warp each)
    edge_kernel<<<(NEDGES + 7) / 8, 256>>>(edge_dst, edge_src, out);

    // Finalize: one thread per float4 of out
    const int nt = NNODES * (FEAT / 4);
    finalize_kernel<<<(nt + 255) / 256, 256>>>(out);
}